// round 1
// baseline (speedup 1.0000x reference)
#include <cuda_runtime.h>
#include <math.h>

// Problem constants (from reference): N=50000, E=400000, d=64
#define MAXN 50000
#define MAXE 400000

// ---------------- static scratch (no allocation allowed) ----------------
__device__ float g_H[MAXN * 256];     // GEMM output buffer (max width 256)
__device__ float g_A[MAXN * 256];     // conv output buffer 1
__device__ float g_B[MAXN * 256];     // conv output buffer 2
__device__ float g_dis[MAXN];         // rsqrt(deg+1)
__device__ int   g_cnt[MAXN];         // in-degree counts
__device__ int   g_rowptr[MAXN + 1];  // CSR row pointers (by dst)
__device__ int   g_cursor[MAXN];      // scatter cursors
__device__ int   g_csrsrc[MAXE];      // CSR src indices
__device__ float g_csrnorm[MAXE];     // per-edge norm dis[src]*dis[dst]
__device__ int   g_mv[256];           // column max (float bits, shifted +2)
__device__ float g_cvec[128];         // mv @ W7[0:256] constant vector

// ---------------- degree count ----------------
__global__ void count_kernel(const int* __restrict__ dst, int e, int* __restrict__ cnt) {
    int i = blockIdx.x * blockDim.x + threadIdx.x;
    if (i < e) atomicAdd(&cnt[dst[i]], 1);
}

// ---------------- single-block exclusive scan + dis ----------------
__global__ void scan_kernel(const int* __restrict__ cnt, int n,
                            int* __restrict__ rowptr, int* __restrict__ cursor,
                            float* __restrict__ dis) {
    __shared__ int sh[1024];
    int tid = threadIdx.x;
    int run = 0;
    for (int base = 0; base < n; base += 1024) {
        int i = base + tid;
        int v = (i < n) ? cnt[i] : 0;
        sh[tid] = v;
        __syncthreads();
        int val = v;
        for (int off = 1; off < 1024; off <<= 1) {
            int t = (tid >= off) ? sh[tid - off] : 0;
            __syncthreads();
            val += t;
            sh[tid] = val;
            __syncthreads();
        }
        if (i < n) {
            int excl = run + val - v;
            rowptr[i] = excl;
            cursor[i] = excl;
            dis[i] = rsqrtf((float)(v + 1));
        }
        int tot = sh[1023];
        __syncthreads();
        run += tot;
    }
    if (tid == 0) rowptr[n] = run;
}

// ---------------- CSR fill ----------------
__global__ void fill_kernel(const int* __restrict__ src, const int* __restrict__ dst, int e,
                            int* __restrict__ cursor, int* __restrict__ csrsrc,
                            float* __restrict__ csrnorm, const float* __restrict__ dis) {
    int i = blockIdx.x * blockDim.x + threadIdx.x;
    if (i >= e) return;
    int d = dst[i];
    int s = src[i];
    int p = atomicAdd(&cursor[d], 1);
    csrsrc[p] = s;
    csrnorm[p] = dis[s] * dis[d];
}

// ---------------- tiled SGEMM: C[n,ncol] (+=) A[n,K] @ W[K,ncol] (+ addvec) ----
// BM=64, BN=64, BK=16, 256 threads, 4x4 per thread. K % 16 == 0, ncol % 64 == 0.
__global__ void sgemm_kernel(const float* __restrict__ A, const float* __restrict__ W,
                             float* __restrict__ C, int n, int K, int ncol,
                             const float* __restrict__ addvec, int accumulate) {
    __shared__ float As[16][64];
    __shared__ float Bs[16][64];
    int tid = threadIdx.x;
    int tx = tid % 16, ty = tid / 16;
    int rowBase = blockIdx.x * 64;
    int colBase = blockIdx.y * 64;

    float acc[4][4];
#pragma unroll
    for (int i = 0; i < 4; i++)
#pragma unroll
        for (int j = 0; j < 4; j++) acc[i][j] = 0.0f;

    int aRow = tid / 4;           // 0..63
    int aCol4 = (tid % 4) * 4;    // 0,4,8,12
    int bRow = tid / 16;          // 0..15
    int bCol4 = (tid % 16) * 4;   // 0..60

    for (int k0 = 0; k0 < K; k0 += 16) {
        int grow = rowBase + aRow;
        float4 a;
        if (grow < n) a = *(const float4*)(A + (size_t)grow * K + k0 + aCol4);
        else          a = make_float4(0.f, 0.f, 0.f, 0.f);
        As[aCol4 + 0][aRow] = a.x;
        As[aCol4 + 1][aRow] = a.y;
        As[aCol4 + 2][aRow] = a.z;
        As[aCol4 + 3][aRow] = a.w;

        float4 b = *(const float4*)(W + (size_t)(k0 + bRow) * ncol + colBase + bCol4);
        Bs[bRow][bCol4 + 0] = b.x;
        Bs[bRow][bCol4 + 1] = b.y;
        Bs[bRow][bCol4 + 2] = b.z;
        Bs[bRow][bCol4 + 3] = b.w;
        __syncthreads();

#pragma unroll
        for (int k = 0; k < 16; k++) {
            float ra[4], rb[4];
#pragma unroll
            for (int i = 0; i < 4; i++) ra[i] = As[k][ty * 4 + i];
#pragma unroll
            for (int j = 0; j < 4; j++) rb[j] = Bs[k][tx * 4 + j];
#pragma unroll
            for (int i = 0; i < 4; i++)
#pragma unroll
                for (int j = 0; j < 4; j++) acc[i][j] += ra[i] * rb[j];
        }
        __syncthreads();
    }

#pragma unroll
    for (int i = 0; i < 4; i++) {
        int row = rowBase + ty * 4 + i;
        if (row >= n) continue;
#pragma unroll
        for (int j = 0; j < 4; j++) {
            int col = colBase + tx * 4 + j;
            float v = acc[i][j];
            if (addvec) v += addvec[col];
            size_t off = (size_t)row * ncol + col;
            if (accumulate) v += C[off];
            C[off] = v;
        }
    }
}

// ---------------- aggregation: out = tanh(sum_nbr h[src]*norm + h[i]*dis^2 + b) ----
template <int F>
__global__ void agg_kernel(const float* __restrict__ h, const int* __restrict__ rowptr,
                           const int* __restrict__ csrsrc, const float* __restrict__ csrnorm,
                           const float* __restrict__ dis, const float* __restrict__ bias,
                           float* __restrict__ out, int n) {
    int warp = (blockIdx.x * blockDim.x + threadIdx.x) >> 5;
    int lane = threadIdx.x & 31;
    if (warp >= n) return;
    constexpr int C = F / 128;  // float4 chunks per lane
    float4 acc[C];
#pragma unroll
    for (int c = 0; c < C; c++) acc[c] = make_float4(0.f, 0.f, 0.f, 0.f);

    int s0 = rowptr[warp], s1 = rowptr[warp + 1];
    for (int j = s0; j < s1; j++) {
        int s = csrsrc[j];
        float w = csrnorm[j];
        const float* hp = h + (size_t)s * F;
#pragma unroll
        for (int c = 0; c < C; c++) {
            float4 v = *(const float4*)(hp + ((lane + 32 * c) << 2));
            acc[c].x += v.x * w;
            acc[c].y += v.y * w;
            acc[c].z += v.z * w;
            acc[c].w += v.w * w;
        }
    }
    float ds = dis[warp];
    float w2 = ds * ds;
    const float* hp = h + (size_t)warp * F;
    float* op = out + (size_t)warp * F;
#pragma unroll
    for (int c = 0; c < C; c++) {
        int idx = (lane + 32 * c) << 2;
        float4 v = *(const float4*)(hp + idx);
        float4 bb = *(const float4*)(bias + idx);
        float4 r;
        r.x = tanhf(acc[c].x + v.x * w2 + bb.x);
        r.y = tanhf(acc[c].y + v.y * w2 + bb.y);
        r.z = tanhf(acc[c].z + v.z * w2 + bb.z);
        r.w = tanhf(acc[c].w + v.w * w2 + bb.w);
        *(float4*)(op + idx) = r;
    }
}

// ---------------- column max over [n,256] (values in (-1,1); shift +2 > 0) ----
__global__ void colmax_kernel(const float* __restrict__ B, int n, int* __restrict__ mv) {
    int col = threadIdx.x;  // 256 threads
    float m = -1e30f;
    for (int r = blockIdx.x; r < n; r += gridDim.x)
        m = fmaxf(m, B[(size_t)r * 256 + col]);
    atomicMax(&mv[col], __float_as_int(m + 2.0f));
}

// ---------------- cvec[j] = sum_k (mv[k]-2) * W7[k,j] over first 256 rows ----
__global__ void cvec_kernel(const int* __restrict__ mv, const float* __restrict__ W7,
                            float* __restrict__ cvec) {
    int j = threadIdx.x;  // 128 threads
    float s = 0.0f;
    for (int k = 0; k < 256; k++)
        s += (__int_as_float(mv[k]) - 2.0f) * W7[(size_t)k * 128 + j];
    cvec[j] = s;
}

extern "C" void kernel_launch(void* const* d_in, const int* in_sizes, int n_in,
                              void* d_out, int out_size) {
    const float* x  = (const float*)d_in[0];
    const int*   ei = (const int*)d_in[1];
    // d_in[2] = batch (unused: segment_max->max == global max)
    const float* W1 = (const float*)d_in[3];
    const float* b1 = (const float*)d_in[4];
    const float* W2 = (const float*)d_in[5];
    const float* b2 = (const float*)d_in[6];
    const float* W3 = (const float*)d_in[7];
    const float* b3 = (const float*)d_in[8];
    const float* W4 = (const float*)d_in[9];
    const float* b4 = (const float*)d_in[10];
    const float* W7 = (const float*)d_in[11];
    const float* b7 = (const float*)d_in[12];

    int n = in_sizes[0] / 64;
    int e = in_sizes[1] / 2;
    const int* src = ei;
    const int* dst = ei + e;
    float* out = (float*)d_out;

    float *H, *A, *B, *dis, *csrnorm, *cvec;
    int *cnt, *rowptr, *cursor, *csrsrc, *mv;
    cudaGetSymbolAddress((void**)&H, g_H);
    cudaGetSymbolAddress((void**)&A, g_A);
    cudaGetSymbolAddress((void**)&B, g_B);
    cudaGetSymbolAddress((void**)&dis, g_dis);
    cudaGetSymbolAddress((void**)&cnt, g_cnt);
    cudaGetSymbolAddress((void**)&rowptr, g_rowptr);
    cudaGetSymbolAddress((void**)&cursor, g_cursor);
    cudaGetSymbolAddress((void**)&csrsrc, g_csrsrc);
    cudaGetSymbolAddress((void**)&csrnorm, g_csrnorm);
    cudaGetSymbolAddress((void**)&mv, g_mv);
    cudaGetSymbolAddress((void**)&cvec, g_cvec);

    int eb = (e + 255) / 256;
    int aggBlocks = (n + 3) / 4;  // 4 warps/block (128 threads), 1 warp per node
    dim3 gemmGrid128((n + 63) / 64, 2);
    dim3 gemmGrid256((n + 63) / 64, 4);

    // --- build degree/norm + CSR ---
    cudaMemsetAsync(cnt, 0, (size_t)n * sizeof(int));
    count_kernel<<<eb, 256>>>(dst, e, cnt);
    scan_kernel<<<1, 1024>>>(cnt, n, rowptr, cursor, dis);
    fill_kernel<<<eb, 256>>>(src, dst, e, cursor, csrsrc, csrnorm, dis);

    // --- branch 1: conv1 (x->128), conv2 (->256) ---
    sgemm_kernel<<<gemmGrid128, 256>>>(x, W1, H, n, 64, 128, nullptr, 0);
    agg_kernel<128><<<aggBlocks, 128>>>(H, rowptr, csrsrc, csrnorm, dis, b1, A, n);
    sgemm_kernel<<<gemmGrid256, 256>>>(A, W2, H, n, 128, 256, nullptr, 0);
    agg_kernel<256><<<aggBlocks, 128>>>(H, rowptr, csrsrc, csrnorm, dis, b2, B, n);

    // --- global column max of branch 1 + constant vector through W7[0:256] ---
    cudaMemsetAsync(mv, 0, 256 * sizeof(int));
    colmax_kernel<<<512, 256>>>(B, n, mv);
    cvec_kernel<<<1, 128>>>(mv, W7, cvec);

    // --- branch 2: conv3 (x->128), conv4 (->256) ---
    sgemm_kernel<<<gemmGrid128, 256>>>(x, W3, H, n, 64, 128, nullptr, 0);
    agg_kernel<128><<<aggBlocks, 128>>>(H, rowptr, csrsrc, csrnorm, dis, b3, A, n);
    sgemm_kernel<<<gemmGrid256, 256>>>(A, W4, H, n, 128, 256, nullptr, 0);
    agg_kernel<256><<<aggBlocks, 128>>>(H, rowptr, csrsrc, csrnorm, dis, b4, B, n);

    // --- conv7: concat GEMM decomposed (i1 part is the constant cvec) ---
    sgemm_kernel<<<gemmGrid128, 256>>>(B, W7 + 256 * 128, H, n, 256, 128, cvec, 0);
    sgemm_kernel<<<gemmGrid128, 256>>>(x, W7 + 512 * 128, H, n, 64, 128, nullptr, 1);
    agg_kernel<128><<<aggBlocks, 128>>>(H, rowptr, csrsrc, csrnorm, dis, b7, out, n);
}